// round 7
// baseline (speedup 1.0000x reference)
#include <cuda_runtime.h>
#include <cuda_bf16.h>

#define N_NODES 50000
#define N_EDGES 800000
#define F1 128
#define F2 16

#define TILE 512
#define NB   ((N_NODES + TILE - 1) / TILE)   // 98

// Scratch (allocation-free contract: __device__ globals)
__device__ int       g_cnt [N_NODES];        // zero at load; self-re-zeroed
__device__ int       g_off [N_NODES];        // exclusive offsets; mutated by fill
__device__ long long g_state[NB];            // scan lookback: [63:32]=flag [31:0]=val
__device__ int       g_src [N_EDGES];
__device__ float     g_dinv[N_NODES];
__device__ float4    g_h1  [N_NODES * (F1 / 4)];
__device__ float4    g_h2  [N_NODES * (F2 / 4)];

// ---------------------------------------------------------------------------
// 1) in-degree counts (edge_index int32; col = second half). int4 reads.
// ---------------------------------------------------------------------------
__global__ void k_count(const int* __restrict__ ei) {
    int e4 = blockIdx.x * blockDim.x + threadIdx.x;
    if (e4 < N_EDGES / 4) {
        int4 c = ((const int4*)(ei + N_EDGES))[e4];
        if ((unsigned)c.x < N_NODES) atomicAdd(&g_cnt[c.x], 1);
        if ((unsigned)c.y < N_NODES) atomicAdd(&g_cnt[c.y], 1);
        if ((unsigned)c.z < N_NODES) atomicAdd(&g_cnt[c.z], 1);
        if ((unsigned)c.w < N_NODES) atomicAdd(&g_cnt[c.w], 1);
    }
}

// ---------------------------------------------------------------------------
// 2) single-kernel scan with decoupled lookback (98 blocks, all wave-1).
//    Fused: dinv = rsqrt(cnt+1); g_cnt self-zeroed (replay determinism).
// ---------------------------------------------------------------------------
__global__ __launch_bounds__(TILE) void k_scan() {
    __shared__ int sh[TILE];
    __shared__ int s_ex;
    int t = threadIdx.x, bid = blockIdx.x;
    int i = bid * TILE + t;

    int c = (i < N_NODES) ? g_cnt[i] : 0;
    if (i < N_NODES) { g_dinv[i] = rsqrtf((float)(c + 1)); g_cnt[i] = 0; }

    sh[t] = c;
    __syncthreads();
    #pragma unroll
    for (int off = 1; off < TILE; off <<= 1) {
        int u = (t >= off) ? sh[t - off] : 0;
        __syncthreads();
        sh[t] += u;
        __syncthreads();
    }
    int total = sh[TILE - 1];

    if (t == 0) {
        long long st = (bid == 0)
            ? ((2LL << 32) | (unsigned)total)
            : ((1LL << 32) | (unsigned)total);
        atomicExch((unsigned long long*)&g_state[bid], (unsigned long long)st);
        if (bid == 0) s_ex = 0;
    }

    if (bid > 0 && t < 32) {
        int ex = 0, base = bid - 1;
        while (true) {
            int j = base - t;
            long long st;
            if (j >= 0) st = *(volatile long long*)&g_state[j];
            else        st = (2LL << 32);
            int flag = (int)(st >> 32);
            int val  = (int)(st & 0xffffffffLL);
            unsigned rdy = __ballot_sync(0xffffffffu, flag != 0);
            if (rdy != 0xffffffffu) continue;
            unsigned pref = __ballot_sync(0xffffffffu, flag == 2);
            int firstP = (pref == 0) ? 32 : (__ffs(pref) - 1);
            int contrib = (t <= firstP) ? val : 0;
            #pragma unroll
            for (int o = 16; o >= 1; o >>= 1)
                contrib += __shfl_xor_sync(0xffffffffu, contrib, o);
            ex += contrib;
            if (firstP < 32) break;
            base -= 32;
        }
        if (t == 0) {
            s_ex = ex;
            atomicExch((unsigned long long*)&g_state[bid],
                       (unsigned long long)((2LL << 32) | (unsigned)(ex + total)));
        }
    }
    __syncthreads();
    if (i < N_NODES) g_off[i] = s_ex + sh[t] - c;
}

// ---------------------------------------------------------------------------
// 3) fill source lists (atomic bump of g_off); re-zero g_state for replay.
// ---------------------------------------------------------------------------
__global__ void k_fill(const int* __restrict__ ei) {
    int t = blockIdx.x * blockDim.x + threadIdx.x;
    if (t < NB) g_state[t] = 0;
    if (t < N_EDGES / 4) {
        int4 r = ((const int4*)ei)[t];
        int4 c = ((const int4*)(ei + N_EDGES))[t];
        if ((unsigned)r.x < N_NODES && (unsigned)c.x < N_NODES)
            g_src[atomicAdd(&g_off[c.x], 1)] = r.x;
        if ((unsigned)r.y < N_NODES && (unsigned)c.y < N_NODES)
            g_src[atomicAdd(&g_off[c.y], 1)] = r.y;
        if ((unsigned)r.z < N_NODES && (unsigned)c.z < N_NODES)
            g_src[atomicAdd(&g_off[c.z], 1)] = r.z;
        if ((unsigned)r.w < N_NODES && (unsigned)c.w < N_NODES)
            g_src[atomicAdd(&g_off[c.w], 1)] = r.w;
    }
}

// ---------------------------------------------------------------------------
// 4) h1 = x @ W1 via tf32 mma.sync (m16n8k8).
//    tf32 conversion done ONCE at smem staging -> inner loop = LDS + MMA only.
// ---------------------------------------------------------------------------
__device__ __forceinline__ float f2tf32_bits(float f) {
    unsigned u;
    asm("cvt.rna.tf32.f32 %0, %1;" : "=r"(u) : "f"(f));
    return __uint_as_float(u);
}

__global__ __launch_bounds__(256) void k_gemm1(const float* __restrict__ x,
                                               const float* __restrict__ W) {
    __shared__ float xs[128 * 36];   // 128 rows x 32 cols (tf32 bits), stride 36
    __shared__ float ws[32 * 136];   // 32 rows x 128 cols (tf32 bits), stride 136

    const int tid  = threadIdx.x;
    const int warp = tid >> 5;
    const int lane = tid & 31;
    const int g    = lane >> 2;
    const int tig  = lane & 3;
    const int row0 = blockIdx.x * 128;

    float c[16][4];
    #pragma unroll
    for (int nt = 0; nt < 16; nt++)
        #pragma unroll
        for (int q = 0; q < 4; q++) c[nt][q] = 0.f;

    const float4* x4 = (const float4*)x;
    const float4* W4 = (const float4*)W;

    for (int kc = 0; kc < 4; kc++) {
        #pragma unroll
        for (int it = 0; it < 4; it++) {
            int idx = it * 256 + tid;
            int r   = idx >> 3;
            int c4  = idx & 7;
            float4 v = make_float4(0.f, 0.f, 0.f, 0.f);
            if (row0 + r < N_NODES)
                v = x4[(size_t)(row0 + r) * 32 + kc * 8 + c4];
            float* d = &xs[r * 36 + c4 * 4];
            d[0] = f2tf32_bits(v.x); d[1] = f2tf32_bits(v.y);
            d[2] = f2tf32_bits(v.z); d[3] = f2tf32_bits(v.w);
        }
        #pragma unroll
        for (int it = 0; it < 4; it++) {
            int idx = it * 256 + tid;
            int k   = idx >> 5;
            int n4  = idx & 31;
            float4 v = W4[(kc * 32 + k) * 32 + n4];
            float* d = &ws[k * 136 + n4 * 4];
            d[0] = f2tf32_bits(v.x); d[1] = f2tf32_bits(v.y);
            d[2] = f2tf32_bits(v.z); d[3] = f2tf32_bits(v.w);
        }
        __syncthreads();

        #pragma unroll
        for (int ks = 0; ks < 4; ks++) {
            int ab = (warp * 16 + g) * 36 + ks * 8 + tig;
            unsigned a0 = __float_as_uint(xs[ab]);
            unsigned a1 = __float_as_uint(xs[ab + 8 * 36]);
            unsigned a2 = __float_as_uint(xs[ab + 4]);
            unsigned a3 = __float_as_uint(xs[ab + 8 * 36 + 4]);

            int bb = (ks * 8 + tig) * 136 + g;
            #pragma unroll
            for (int nt = 0; nt < 16; nt++) {
                unsigned b0 = __float_as_uint(ws[bb + nt * 8]);
                unsigned b1 = __float_as_uint(ws[bb + 4 * 136 + nt * 8]);
                asm("mma.sync.aligned.m16n8k8.row.col.f32.tf32.tf32.f32 "
                    "{%0,%1,%2,%3}, {%4,%5,%6,%7}, {%8,%9}, {%0,%1,%2,%3};"
                    : "+f"(c[nt][0]), "+f"(c[nt][1]), "+f"(c[nt][2]), "+f"(c[nt][3])
                    : "r"(a0), "r"(a1), "r"(a2), "r"(a3), "r"(b0), "r"(b1));
            }
        }
        __syncthreads();
    }

    float* h1 = (float*)g_h1;
    int m0 = row0 + warp * 16 + g;
    #pragma unroll
    for (int nt = 0; nt < 16; nt++) {
        int col = nt * 8 + 2 * tig;
        if (m0 < N_NODES)
            *(float2*)&h1[(size_t)m0 * F1 + col] = make_float2(c[nt][0], c[nt][1]);
        if (m0 + 8 < N_NODES)
            *(float2*)&h1[(size_t)(m0 + 8) * F1 + col] = make_float2(c[nt][2], c[nt][3]);
    }
}

// ---------------------------------------------------------------------------
// 5) fused layer-1: gather + self-loop + bias + ReLU + @W2.
//    4-way edge unroll -> MLP=4 on the random row gathers.
// ---------------------------------------------------------------------------
__global__ __launch_bounds__(256) void k_layer1(const float* __restrict__ b1,
                                                const float* __restrict__ W2) {
    int row  = (blockIdx.x * 256 + threadIdx.x) >> 5;
    int lane = threadIdx.x & 31;
    if (row >= N_NODES) return;

    float dc = g_dinv[row];
    float d2 = dc * dc;

    float4 h    = g_h1[row * 32 + lane];
    float4 acc0 = make_float4(h.x * d2, h.y * d2, h.z * d2, h.w * d2);
    float4 acc1 = make_float4(0.f, 0.f, 0.f, 0.f);
    float4 acc2 = make_float4(0.f, 0.f, 0.f, 0.f);
    float4 acc3 = make_float4(0.f, 0.f, 0.f, 0.f);

    int e0 = (row > 0) ? g_off[row - 1] : 0;
    int e1 = g_off[row];
    int e  = e0;

    for (; e + 4 <= e1; e += 4) {
        int r0 = g_src[e + 0], r1 = g_src[e + 1];
        int r2 = g_src[e + 2], r3 = g_src[e + 3];
        float w0 = g_dinv[r0] * dc, w1 = g_dinv[r1] * dc;
        float w2 = g_dinv[r2] * dc, w3 = g_dinv[r3] * dc;
        float4 v0 = g_h1[r0 * 32 + lane];
        float4 v1 = g_h1[r1 * 32 + lane];
        float4 v2 = g_h1[r2 * 32 + lane];
        float4 v3 = g_h1[r3 * 32 + lane];
        acc0.x = fmaf(v0.x, w0, acc0.x); acc0.y = fmaf(v0.y, w0, acc0.y);
        acc0.z = fmaf(v0.z, w0, acc0.z); acc0.w = fmaf(v0.w, w0, acc0.w);
        acc1.x = fmaf(v1.x, w1, acc1.x); acc1.y = fmaf(v1.y, w1, acc1.y);
        acc1.z = fmaf(v1.z, w1, acc1.z); acc1.w = fmaf(v1.w, w1, acc1.w);
        acc2.x = fmaf(v2.x, w2, acc2.x); acc2.y = fmaf(v2.y, w2, acc2.y);
        acc2.z = fmaf(v2.z, w2, acc2.z); acc2.w = fmaf(v2.w, w2, acc2.w);
        acc3.x = fmaf(v3.x, w3, acc3.x); acc3.y = fmaf(v3.y, w3, acc3.y);
        acc3.z = fmaf(v3.z, w3, acc3.z); acc3.w = fmaf(v3.w, w3, acc3.w);
    }
    for (; e < e1; e++) {
        int   r = g_src[e];
        float w = g_dinv[r] * dc;
        float4 v = g_h1[r * 32 + lane];
        acc0.x = fmaf(v.x, w, acc0.x); acc0.y = fmaf(v.y, w, acc0.y);
        acc0.z = fmaf(v.z, w, acc0.z); acc0.w = fmaf(v.w, w, acc0.w);
    }

    acc0.x += acc1.x + acc2.x + acc3.x;
    acc0.y += acc1.y + acc2.y + acc3.y;
    acc0.z += acc1.z + acc2.z + acc3.z;
    acc0.w += acc1.w + acc2.w + acc3.w;

    float4 b = ((const float4*)b1)[lane];
    float v[4];
    v[0] = fmaxf(acc0.x + b.x, 0.f);
    v[1] = fmaxf(acc0.y + b.y, 0.f);
    v[2] = fmaxf(acc0.z + b.z, 0.f);
    v[3] = fmaxf(acc0.w + b.w, 0.f);

    float p[16];
    #pragma unroll
    for (int j = 0; j < 16; j++) p[j] = 0.f;

    #pragma unroll
    for (int q = 0; q < 4; q++) {
        int k = lane * 4 + q;
        #pragma unroll
        for (int j4 = 0; j4 < 4; j4++) {
            float4 ww = ((const float4*)W2)[k * 4 + j4];
            p[j4 * 4 + 0] = fmaf(v[q], ww.x, p[j4 * 4 + 0]);
            p[j4 * 4 + 1] = fmaf(v[q], ww.y, p[j4 * 4 + 1]);
            p[j4 * 4 + 2] = fmaf(v[q], ww.z, p[j4 * 4 + 2]);
            p[j4 * 4 + 3] = fmaf(v[q], ww.w, p[j4 * 4 + 3]);
        }
    }

    #pragma unroll
    for (int off = 16; off >= 1; off >>= 1)
        #pragma unroll
        for (int j = 0; j < 16; j++)
            p[j] += __shfl_xor_sync(0xffffffffu, p[j], off);

    if (lane < 16) ((float*)g_h2)[row * F2 + lane] = p[lane];
}

// ---------------------------------------------------------------------------
// 6) fused layer-2: gather + self-loop + bias + log_softmax (4-way unroll)
// ---------------------------------------------------------------------------
__global__ __launch_bounds__(256) void k_layer2(const float* __restrict__ b2,
                                                float* __restrict__ out) {
    int row  = (blockIdx.x * 256 + threadIdx.x) >> 5;
    int lane = threadIdx.x & 31;
    if (row >= N_NODES) return;

    int j = lane & 15;
    float dc = g_dinv[row];
    float d2 = dc * dc;

    const float* h2 = (const float*)g_h2;
    float a0 = h2[row * F2 + j] * d2, a1 = 0.f, a2 = 0.f, a3 = 0.f;

    int e0 = (row > 0) ? g_off[row - 1] : 0;
    int e1 = g_off[row];
    int e  = e0;

    for (; e + 4 <= e1; e += 4) {
        int r0 = g_src[e + 0], r1 = g_src[e + 1];
        int r2 = g_src[e + 2], r3 = g_src[e + 3];
        float w0 = g_dinv[r0] * dc, w1 = g_dinv[r1] * dc;
        float w2 = g_dinv[r2] * dc, w3 = g_dinv[r3] * dc;
        a0 = fmaf(h2[r0 * F2 + j], w0, a0);
        a1 = fmaf(h2[r1 * F2 + j], w1, a1);
        a2 = fmaf(h2[r2 * F2 + j], w2, a2);
        a3 = fmaf(h2[r3 * F2 + j], w3, a3);
    }
    for (; e < e1; e++) {
        int   r = g_src[e];
        float w = g_dinv[r] * dc;
        a0 = fmaf(h2[r * F2 + j], w, a0);
    }

    float acc = a0 + a1 + a2 + a3 + b2[j];

    float m = acc;
    #pragma unroll
    for (int off = 8; off >= 1; off >>= 1)
        m = fmaxf(m, __shfl_xor_sync(0xffffffffu, m, off));

    float s = __expf(acc - m);
    #pragma unroll
    for (int off = 8; off >= 1; off >>= 1)
        s += __shfl_xor_sync(0xffffffffu, s, off);

    if (lane < 16) out[row * F2 + lane] = (acc - m) - logf(s);
}

// ---------------------------------------------------------------------------
extern "C" void kernel_launch(void* const* d_in, const int* in_sizes, int n_in,
                              void* d_out, int out_size) {
    const float* x  = (const float*)d_in[0];
    const int*   ei = (const int*)d_in[1];     // int32 (JAX x64 disabled)
    const float* W1 = (const float*)d_in[2];
    const float* b1 = (const float*)d_in[3];
    const float* W2 = (const float*)d_in[4];
    const float* b2 = (const float*)d_in[5];
    float* out = (float*)d_out;

    (void)in_sizes; (void)n_in; (void)out_size;

    k_count <<<(N_EDGES / 4 + 255) / 256, 256>>>(ei);
    k_scan  <<<NB, TILE>>>();
    k_fill  <<<(N_EDGES / 4 + 255) / 256, 256>>>(ei);
    k_gemm1 <<<(N_NODES + 127) / 128, 256>>>(x, W1);
    k_layer1<<<(N_NODES * 32 + 255) / 256, 256>>>(b1, W2);
    k_layer2<<<(N_NODES * 32 + 255) / 256, 256>>>(b2, out);
}

// round 9
// speedup vs baseline: 1.0645x; 1.0645x over previous
#include <cuda_runtime.h>
#include <cuda_fp16.h>

#define N_NODES 50000
#define N_EDGES 800000
#define F1 128
#define F2 16

#define TILE 512
#define NB   ((N_NODES + TILE - 1) / TILE)   // 98

// Scratch (allocation-free contract: __device__ globals)
__device__ int       g_cnt [N_NODES];        // zero at load; self-re-zeroed
__device__ int       g_off [N_NODES];        // exclusive offsets; mutated by fill
__device__ long long g_state[NB];            // scan lookback: [63:32]=flag [31:0]=val
__device__ int       g_src [N_EDGES];
__device__ float     g_dinv[N_NODES];
__device__ __align__(16) __half2 g_h1h[N_NODES * (F1 / 2)];  // h1 in fp16 (gather traffic /2)
__device__ float4    g_h2  [N_NODES * (F2 / 4)];

// ---------------------------------------------------------------------------
// 1) in-degree counts (edge_index int32; col = second half). int4 reads.
// ---------------------------------------------------------------------------
__global__ void k_count(const int* __restrict__ ei) {
    int e4 = blockIdx.x * blockDim.x + threadIdx.x;
    if (e4 < N_EDGES / 4) {
        int4 c = ((const int4*)(ei + N_EDGES))[e4];
        if ((unsigned)c.x < N_NODES) atomicAdd(&g_cnt[c.x], 1);
        if ((unsigned)c.y < N_NODES) atomicAdd(&g_cnt[c.y], 1);
        if ((unsigned)c.z < N_NODES) atomicAdd(&g_cnt[c.z], 1);
        if ((unsigned)c.w < N_NODES) atomicAdd(&g_cnt[c.w], 1);
    }
}

// ---------------------------------------------------------------------------
// 2) single-kernel scan with decoupled lookback (98 blocks, all wave-1).
//    Fused: dinv = rsqrt(cnt+1); g_cnt self-zeroed (replay determinism).
// ---------------------------------------------------------------------------
__global__ __launch_bounds__(TILE) void k_scan() {
    __shared__ int sh[TILE];
    __shared__ int s_ex;
    int t = threadIdx.x, bid = blockIdx.x;
    int i = bid * TILE + t;

    int c = (i < N_NODES) ? g_cnt[i] : 0;
    if (i < N_NODES) { g_dinv[i] = rsqrtf((float)(c + 1)); g_cnt[i] = 0; }

    sh[t] = c;
    __syncthreads();
    #pragma unroll
    for (int off = 1; off < TILE; off <<= 1) {
        int u = (t >= off) ? sh[t - off] : 0;
        __syncthreads();
        sh[t] += u;
        __syncthreads();
    }
    int total = sh[TILE - 1];

    if (t == 0) {
        long long st = (bid == 0)
            ? ((2LL << 32) | (unsigned)total)
            : ((1LL << 32) | (unsigned)total);
        atomicExch((unsigned long long*)&g_state[bid], (unsigned long long)st);
        if (bid == 0) s_ex = 0;
    }

    if (bid > 0 && t < 32) {
        int ex = 0, base = bid - 1;
        while (true) {
            int j = base - t;
            long long st;
            if (j >= 0) st = *(volatile long long*)&g_state[j];
            else        st = (2LL << 32);
            int flag = (int)(st >> 32);
            int val  = (int)(st & 0xffffffffLL);
            unsigned rdy = __ballot_sync(0xffffffffu, flag != 0);
            if (rdy != 0xffffffffu) continue;
            unsigned pref = __ballot_sync(0xffffffffu, flag == 2);
            int firstP = (pref == 0) ? 32 : (__ffs(pref) - 1);
            int contrib = (t <= firstP) ? val : 0;
            #pragma unroll
            for (int o = 16; o >= 1; o >>= 1)
                contrib += __shfl_xor_sync(0xffffffffu, contrib, o);
            ex += contrib;
            if (firstP < 32) break;
            base -= 32;
        }
        if (t == 0) {
            s_ex = ex;
            atomicExch((unsigned long long*)&g_state[bid],
                       (unsigned long long)((2LL << 32) | (unsigned)(ex + total)));
        }
    }
    __syncthreads();
    if (i < N_NODES) g_off[i] = s_ex + sh[t] - c;
}

// ---------------------------------------------------------------------------
// 3) fill source lists (atomic bump of g_off); re-zero g_state for replay.
// ---------------------------------------------------------------------------
__global__ void k_fill(const int* __restrict__ ei) {
    int t = blockIdx.x * blockDim.x + threadIdx.x;
    if (t < NB) g_state[t] = 0;
    if (t < N_EDGES / 4) {
        int4 r = ((const int4*)ei)[t];
        int4 c = ((const int4*)(ei + N_EDGES))[t];
        if ((unsigned)r.x < N_NODES && (unsigned)c.x < N_NODES)
            g_src[atomicAdd(&g_off[c.x], 1)] = r.x;
        if ((unsigned)r.y < N_NODES && (unsigned)c.y < N_NODES)
            g_src[atomicAdd(&g_off[c.y], 1)] = r.y;
        if ((unsigned)r.z < N_NODES && (unsigned)c.z < N_NODES)
            g_src[atomicAdd(&g_off[c.z], 1)] = r.z;
        if ((unsigned)r.w < N_NODES && (unsigned)c.w < N_NODES)
            g_src[atomicAdd(&g_off[c.w], 1)] = r.w;
    }
}

// ---------------------------------------------------------------------------
// 4) h1 = x @ W1 via tf32 mma.sync (m16n8k8); epilogue converts to fp16.
// ---------------------------------------------------------------------------
__device__ __forceinline__ float f2tf32_bits(float f) {
    unsigned u;
    asm("cvt.rna.tf32.f32 %0, %1;" : "=r"(u) : "f"(f));
    return __uint_as_float(u);
}

__global__ __launch_bounds__(256) void k_gemm1(const float* __restrict__ x,
                                               const float* __restrict__ W) {
    __shared__ float xs[128 * 36];   // 128 rows x 32 cols (tf32 bits), stride 36
    __shared__ float ws[32 * 136];   // 32 rows x 128 cols (tf32 bits), stride 136

    const int tid  = threadIdx.x;
    const int warp = tid >> 5;
    const int lane = tid & 31;
    const int g    = lane >> 2;
    const int tig  = lane & 3;
    const int row0 = blockIdx.x * 128;

    float c[16][4];
    #pragma unroll
    for (int nt = 0; nt < 16; nt++)
        #pragma unroll
        for (int q = 0; q < 4; q++) c[nt][q] = 0.f;

    const float4* x4 = (const float4*)x;
    const float4* W4 = (const float4*)W;

    for (int kc = 0; kc < 4; kc++) {
        #pragma unroll
        for (int it = 0; it < 4; it++) {
            int idx = it * 256 + tid;
            int r   = idx >> 3;
            int c4  = idx & 7;
            float4 v = make_float4(0.f, 0.f, 0.f, 0.f);
            if (row0 + r < N_NODES)
                v = x4[(size_t)(row0 + r) * 32 + kc * 8 + c4];
            float* d = &xs[r * 36 + c4 * 4];
            d[0] = f2tf32_bits(v.x); d[1] = f2tf32_bits(v.y);
            d[2] = f2tf32_bits(v.z); d[3] = f2tf32_bits(v.w);
        }
        #pragma unroll
        for (int it = 0; it < 4; it++) {
            int idx = it * 256 + tid;
            int k   = idx >> 5;
            int n4  = idx & 31;
            float4 v = W4[(kc * 32 + k) * 32 + n4];
            float* d = &ws[k * 136 + n4 * 4];
            d[0] = f2tf32_bits(v.x); d[1] = f2tf32_bits(v.y);
            d[2] = f2tf32_bits(v.z); d[3] = f2tf32_bits(v.w);
        }
        __syncthreads();

        #pragma unroll
        for (int ks = 0; ks < 4; ks++) {
            int ab = (warp * 16 + g) * 36 + ks * 8 + tig;
            unsigned a0 = __float_as_uint(xs[ab]);
            unsigned a1 = __float_as_uint(xs[ab + 8 * 36]);
            unsigned a2 = __float_as_uint(xs[ab + 4]);
            unsigned a3 = __float_as_uint(xs[ab + 8 * 36 + 4]);

            int bb = (ks * 8 + tig) * 136 + g;
            #pragma unroll
            for (int nt = 0; nt < 16; nt++) {
                unsigned b0 = __float_as_uint(ws[bb + nt * 8]);
                unsigned b1 = __float_as_uint(ws[bb + 4 * 136 + nt * 8]);
                asm("mma.sync.aligned.m16n8k8.row.col.f32.tf32.tf32.f32 "
                    "{%0,%1,%2,%3}, {%4,%5,%6,%7}, {%8,%9}, {%0,%1,%2,%3};"
                    : "+f"(c[nt][0]), "+f"(c[nt][1]), "+f"(c[nt][2]), "+f"(c[nt][3])
                    : "r"(a0), "r"(a1), "r"(a2), "r"(a3), "r"(b0), "r"(b1));
            }
        }
        __syncthreads();
    }

    // store fp16: C frag m16n8 -> rows (g, g+8), cols (2*tig, 2*tig+1)
    int m0 = row0 + warp * 16 + g;
    #pragma unroll
    for (int nt = 0; nt < 16; nt++) {
        int c2 = nt * 4 + tig;                       // half2 column index (of 64)
        if (m0 < N_NODES)
            g_h1h[(size_t)m0 * 64 + c2] = __floats2half2_rn(c[nt][0], c[nt][1]);
        if (m0 + 8 < N_NODES)
            g_h1h[(size_t)(m0 + 8) * 64 + c2] = __floats2half2_rn(c[nt][2], c[nt][3]);
    }
}

// ---------------------------------------------------------------------------
// 5) fused layer-1: fp16 gather + self-loop + bias + ReLU + @W2.
//    one warp per node; lane loads 8 B (4 halfs) per source row.
// ---------------------------------------------------------------------------
__global__ __launch_bounds__(256) void k_layer1(const float* __restrict__ b1,
                                                const float* __restrict__ W2) {
    int row  = (blockIdx.x * 256 + threadIdx.x) >> 5;
    int lane = threadIdx.x & 31;
    if (row >= N_NODES) return;

    float dc = g_dinv[row];
    float d2 = dc * dc;

    const uint2* h1v = (const uint2*)g_h1h;     // 4 halfs per element

    uint2  su = h1v[(size_t)row * 32 + lane];
    float2 s0 = __half22float2(*(__half2*)&su.x);
    float2 s1 = __half22float2(*(__half2*)&su.y);
    float4 acc = make_float4(s0.x * d2, s0.y * d2, s1.x * d2, s1.y * d2);

    int e0 = (row > 0) ? g_off[row - 1] : 0;
    int e1 = g_off[row];
    for (int e = e0; e < e1; e++) {
        int   r = g_src[e];                     // warp-uniform
        float w = g_dinv[r] * dc;
        uint2  u  = h1v[(size_t)r * 32 + lane];
        float2 v0 = __half22float2(*(__half2*)&u.x);
        float2 v1 = __half22float2(*(__half2*)&u.y);
        acc.x = fmaf(v0.x, w, acc.x);
        acc.y = fmaf(v0.y, w, acc.y);
        acc.z = fmaf(v1.x, w, acc.z);
        acc.w = fmaf(v1.y, w, acc.w);
    }

    float4 b = ((const float4*)b1)[lane];
    float v[4];
    v[0] = fmaxf(acc.x + b.x, 0.f);
    v[1] = fmaxf(acc.y + b.y, 0.f);
    v[2] = fmaxf(acc.z + b.z, 0.f);
    v[3] = fmaxf(acc.w + b.w, 0.f);

    float p[16];
    #pragma unroll
    for (int j = 0; j < 16; j++) p[j] = 0.f;

    #pragma unroll
    for (int q = 0; q < 4; q++) {
        int k = lane * 4 + q;
        #pragma unroll
        for (int j4 = 0; j4 < 4; j4++) {
            float4 ww = ((const float4*)W2)[k * 4 + j4];
            p[j4 * 4 + 0] = fmaf(v[q], ww.x, p[j4 * 4 + 0]);
            p[j4 * 4 + 1] = fmaf(v[q], ww.y, p[j4 * 4 + 1]);
            p[j4 * 4 + 2] = fmaf(v[q], ww.z, p[j4 * 4 + 2]);
            p[j4 * 4 + 3] = fmaf(v[q], ww.w, p[j4 * 4 + 3]);
        }
    }

    #pragma unroll
    for (int off = 16; off >= 1; off >>= 1)
        #pragma unroll
        for (int j = 0; j < 16; j++)
            p[j] += __shfl_xor_sync(0xffffffffu, p[j], off);

    if (lane < 16) ((float*)g_h2)[row * F2 + lane] = p[lane];
}

// ---------------------------------------------------------------------------
// 6) fused layer-2: gather + self-loop + bias + log_softmax
// ---------------------------------------------------------------------------
__global__ __launch_bounds__(256) void k_layer2(const float* __restrict__ b2,
                                                float* __restrict__ out) {
    int row  = (blockIdx.x * 256 + threadIdx.x) >> 5;
    int lane = threadIdx.x & 31;
    if (row >= N_NODES) return;

    int j = lane & 15;
    float dc = g_dinv[row];
    float d2 = dc * dc;

    const float* h2 = (const float*)g_h2;
    float acc = h2[row * F2 + j] * d2;

    int e0 = (row > 0) ? g_off[row - 1] : 0;
    int e1 = g_off[row];
    for (int e = e0; e < e1; e++) {
        int   r = g_src[e];
        float w = g_dinv[r] * dc;
        acc = fmaf(h2[r * F2 + j], w, acc);
    }
    acc += b2[j];

    float m = acc;
    #pragma unroll
    for (int off = 8; off >= 1; off >>= 1)
        m = fmaxf(m, __shfl_xor_sync(0xffffffffu, m, off));

    float s = __expf(acc - m);
    #pragma unroll
    for (int off = 8; off >= 1; off >>= 1)
        s += __shfl_xor_sync(0xffffffffu, s, off);

    if (lane < 16) out[row * F2 + lane] = (acc - m) - logf(s);
}

// ---------------------------------------------------------------------------
extern "C" void kernel_launch(void* const* d_in, const int* in_sizes, int n_in,
                              void* d_out, int out_size) {
    const float* x  = (const float*)d_in[0];
    const int*   ei = (const int*)d_in[1];     // int32 (JAX x64 disabled)
    const float* W1 = (const float*)d_in[2];
    const float* b1 = (const float*)d_in[3];
    const float* W2 = (const float*)d_in[4];
    const float* b2 = (const float*)d_in[5];
    float* out = (float*)d_out;

    (void)in_sizes; (void)n_in; (void)out_size;

    k_count <<<(N_EDGES / 4 + 255) / 256, 256>>>(ei);
    k_scan  <<<NB, TILE>>>();
    k_fill  <<<(N_EDGES / 4 + 255) / 256, 256>>>(ei);
    k_gemm1 <<<(N_NODES + 127) / 128, 256>>>(x, W1);
    k_layer1<<<(N_NODES * 32 + 255) / 256, 256>>>(b1, W2);
    k_layer2<<<(N_NODES * 32 + 255) / 256, 256>>>(b2, out);
}

// round 14
// speedup vs baseline: 1.1081x; 1.0409x over previous
#include <cuda_runtime.h>
#include <cuda_fp16.h>

#define N_NODES 50000
#define N_EDGES 800000
#define F1 128
#define F2 16

#define TILE 512
#define NB   ((N_NODES + TILE - 1) / TILE)   // 98

// Scratch (allocation-free contract: __device__ globals)
__device__ int       g_cnt [N_NODES];        // zero at load; self-re-zeroed
__device__ int       g_off [N_NODES];        // exclusive offsets; mutated by fill
__device__ long long g_state[NB];            // scan lookback
__device__ int       g_src [N_EDGES];
__device__ float     g_dinv[N_NODES];
__device__ __align__(16) __half2 g_h1h[N_NODES * (F1 / 2)];  // h1 * dinv[row], fp16
__device__ float4    g_h2  [N_NODES * (F2 / 4)];             // h2 * dinv[row], fp32

// ---------------------------------------------------------------------------
// 1) in-degree counts (edge_index int32; col = second half). int4 reads.
// ---------------------------------------------------------------------------
__global__ void k_count(const int* __restrict__ ei) {
    int e4 = blockIdx.x * blockDim.x + threadIdx.x;
    if (e4 < N_EDGES / 4) {
        int4 c = ((const int4*)(ei + N_EDGES))[e4];
        if ((unsigned)c.x < N_NODES) atomicAdd(&g_cnt[c.x], 1);
        if ((unsigned)c.y < N_NODES) atomicAdd(&g_cnt[c.y], 1);
        if ((unsigned)c.z < N_NODES) atomicAdd(&g_cnt[c.z], 1);
        if ((unsigned)c.w < N_NODES) atomicAdd(&g_cnt[c.w], 1);
    }
}

// ---------------------------------------------------------------------------
// 2) single-kernel scan with decoupled lookback (98 blocks, all wave-1).
//    Fused: dinv = rsqrt(cnt+1); g_cnt self-zeroed (replay determinism).
// ---------------------------------------------------------------------------
__global__ __launch_bounds__(TILE) void k_scan() {
    __shared__ int sh[TILE];
    __shared__ int s_ex;
    int t = threadIdx.x, bid = blockIdx.x;
    int i = bid * TILE + t;

    int c = (i < N_NODES) ? g_cnt[i] : 0;
    if (i < N_NODES) { g_dinv[i] = rsqrtf((float)(c + 1)); g_cnt[i] = 0; }

    sh[t] = c;
    __syncthreads();
    #pragma unroll
    for (int off = 1; off < TILE; off <<= 1) {
        int u = (t >= off) ? sh[t - off] : 0;
        __syncthreads();
        sh[t] += u;
        __syncthreads();
    }
    int total = sh[TILE - 1];

    if (t == 0) {
        long long st = (bid == 0)
            ? ((2LL << 32) | (unsigned)total)
            : ((1LL << 32) | (unsigned)total);
        atomicExch((unsigned long long*)&g_state[bid], (unsigned long long)st);
        if (bid == 0) s_ex = 0;
    }

    if (bid > 0 && t < 32) {
        int ex = 0, base = bid - 1;
        while (true) {
            int j = base - t;
            long long st;
            if (j >= 0) st = *(volatile long long*)&g_state[j];
            else        st = (2LL << 32);
            int flag = (int)(st >> 32);
            int val  = (int)(st & 0xffffffffLL);
            unsigned rdy = __ballot_sync(0xffffffffu, flag != 0);
            if (rdy != 0xffffffffu) continue;
            unsigned pref = __ballot_sync(0xffffffffu, flag == 2);
            int firstP = (pref == 0) ? 32 : (__ffs(pref) - 1);
            int contrib = (t <= firstP) ? val : 0;
            #pragma unroll
            for (int o = 16; o >= 1; o >>= 1)
                contrib += __shfl_xor_sync(0xffffffffu, contrib, o);
            ex += contrib;
            if (firstP < 32) break;
            base -= 32;
        }
        if (t == 0) {
            s_ex = ex;
            atomicExch((unsigned long long*)&g_state[bid],
                       (unsigned long long)((2LL << 32) | (unsigned)(ex + total)));
        }
    }
    __syncthreads();
    if (i < N_NODES) g_off[i] = s_ex + sh[t] - c;
}

// ---------------------------------------------------------------------------
// 3) fill source lists (atomic bump of g_off); re-zero g_state for replay.
// ---------------------------------------------------------------------------
__global__ void k_fill(const int* __restrict__ ei) {
    int t = blockIdx.x * blockDim.x + threadIdx.x;
    if (t < NB) g_state[t] = 0;
    if (t < N_EDGES / 4) {
        int4 r = ((const int4*)ei)[t];
        int4 c = ((const int4*)(ei + N_EDGES))[t];
        if ((unsigned)r.x < N_NODES && (unsigned)c.x < N_NODES)
            g_src[atomicAdd(&g_off[c.x], 1)] = r.x;
        if ((unsigned)r.y < N_NODES && (unsigned)c.y < N_NODES)
            g_src[atomicAdd(&g_off[c.y], 1)] = r.y;
        if ((unsigned)r.z < N_NODES && (unsigned)c.z < N_NODES)
            g_src[atomicAdd(&g_off[c.z], 1)] = r.z;
        if ((unsigned)r.w < N_NODES && (unsigned)c.w < N_NODES)
            g_src[atomicAdd(&g_off[c.w], 1)] = r.w;
    }
}

// ---------------------------------------------------------------------------
// 4) h1s = (x @ W1) * dinv[row], fp16, via tf32 mma.sync.
//    128 threads / 64 rows per block -> grid 782 (~1 wave at 5 blocks/SM).
// ---------------------------------------------------------------------------
__device__ __forceinline__ float f2tf32_bits(float f) {
    unsigned u;
    asm("cvt.rna.tf32.f32 %0, %1;" : "=r"(u) : "f"(f));
    return __uint_as_float(u);
}

__global__ __launch_bounds__(128) void k_gemm1(const float* __restrict__ x,
                                               const float* __restrict__ W) {
    __shared__ float xs[64 * 36];    // 64 rows x 32 cols (tf32 bits), stride 36
    __shared__ float ws[32 * 136];   // 32 rows x 128 cols (tf32 bits), stride 136

    const int tid  = threadIdx.x;
    const int warp = tid >> 5;       // 0..3
    const int lane = tid & 31;
    const int g    = lane >> 2;
    const int tig  = lane & 3;
    const int row0 = blockIdx.x * 64;

    float c[16][4];
    #pragma unroll
    for (int nt = 0; nt < 16; nt++)
        #pragma unroll
        for (int q = 0; q < 4; q++) c[nt][q] = 0.f;

    const float4* x4 = (const float4*)x;
    const float4* W4 = (const float4*)W;

    for (int kc = 0; kc < 4; kc++) {
        #pragma unroll
        for (int it = 0; it < 4; it++) {          // 64*8 = 512 float4s
            int idx = it * 128 + tid;
            int r   = idx >> 3;
            int c4  = idx & 7;
            float4 v = make_float4(0.f, 0.f, 0.f, 0.f);
            if (row0 + r < N_NODES)
                v = x4[(size_t)(row0 + r) * 32 + kc * 8 + c4];
            float* d = &xs[r * 36 + c4 * 4];
            d[0] = f2tf32_bits(v.x); d[1] = f2tf32_bits(v.y);
            d[2] = f2tf32_bits(v.z); d[3] = f2tf32_bits(v.w);
        }
        #pragma unroll
        for (int it = 0; it < 8; it++) {          // 32*32 = 1024 float4s
            int idx = it * 128 + tid;
            int k   = idx >> 5;
            int n4  = idx & 31;
            float4 v = W4[(kc * 32 + k) * 32 + n4];
            float* d = &ws[k * 136 + n4 * 4];
            d[0] = f2tf32_bits(v.x); d[1] = f2tf32_bits(v.y);
            d[2] = f2tf32_bits(v.z); d[3] = f2tf32_bits(v.w);
        }
        __syncthreads();

        #pragma unroll
        for (int ks = 0; ks < 4; ks++) {
            int ab = (warp * 16 + g) * 36 + ks * 8 + tig;
            unsigned a0 = __float_as_uint(xs[ab]);
            unsigned a1 = __float_as_uint(xs[ab + 8 * 36]);
            unsigned a2 = __float_as_uint(xs[ab + 4]);
            unsigned a3 = __float_as_uint(xs[ab + 8 * 36 + 4]);

            int bb = (ks * 8 + tig) * 136 + g;
            #pragma unroll
            for (int nt = 0; nt < 16; nt++) {
                unsigned b0 = __float_as_uint(ws[bb + nt * 8]);
                unsigned b1 = __float_as_uint(ws[bb + 4 * 136 + nt * 8]);
                asm("mma.sync.aligned.m16n8k8.row.col.f32.tf32.tf32.f32 "
                    "{%0,%1,%2,%3}, {%4,%5,%6,%7}, {%8,%9}, {%0,%1,%2,%3};"
                    : "+f"(c[nt][0]), "+f"(c[nt][1]), "+f"(c[nt][2]), "+f"(c[nt][3])
                    : "r"(a0), "r"(a1), "r"(a2), "r"(a3), "r"(b0), "r"(b1));
            }
        }
        __syncthreads();
    }

    // store fp16, pre-scaled by dinv[row]
    int ma = row0 + warp * 16 + g;
    int mb = ma + 8;
    float da = (ma < N_NODES) ? g_dinv[ma] : 0.f;
    float db = (mb < N_NODES) ? g_dinv[mb] : 0.f;
    #pragma unroll
    for (int nt = 0; nt < 16; nt++) {
        int c2 = nt * 4 + tig;                       // half2 column (of 64)
        if (ma < N_NODES)
            g_h1h[(size_t)ma * 64 + c2] = __floats2half2_rn(c[nt][0] * da, c[nt][1] * da);
        if (mb < N_NODES)
            g_h1h[(size_t)mb * 64 + c2] = __floats2half2_rn(c[nt][2] * db, c[nt][3] * db);
    }
}

// ---------------------------------------------------------------------------
// 5) fused layer-1: gather pre-scaled h1s + bias + ReLU + @W2.
//    inner loop: src prefetch + single 8B row load (no dinv, no fma weight).
//    agg = dc * (h1s[row] + sum h1s[r]);  h2s[row] = (relu(agg+b1) @ W2) * dc
// ---------------------------------------------------------------------------
__global__ __launch_bounds__(256) void k_layer1(const float* __restrict__ b1,
                                                const float* __restrict__ W2) {
    int row  = (blockIdx.x * 256 + threadIdx.x) >> 5;
    int lane = threadIdx.x & 31;
    if (row >= N_NODES) return;

    float dc = g_dinv[row];

    const uint2* h1v = (const uint2*)g_h1h;     // 4 halfs per element

    uint2  su = h1v[(size_t)row * 32 + lane];
    float2 s0 = __half22float2(*(__half2*)&su.x);
    float2 s1 = __half22float2(*(__half2*)&su.y);
    float4 acc = make_float4(s0.x, s0.y, s1.x, s1.y);   // self term (h1s[row])

    int e0 = (row > 0) ? g_off[row - 1] : 0;
    int e1 = g_off[row];
    int r_nxt = (e0 < e1) ? g_src[e0] : 0;
    for (int e = e0; e < e1; e++) {
        int r = r_nxt;
        r_nxt = g_src[(e + 1 < e1) ? e + 1 : e];        // branchless prefetch
        uint2  u  = h1v[(size_t)r * 32 + lane];
        float2 v0 = __half22float2(*(__half2*)&u.x);
        float2 v1 = __half22float2(*(__half2*)&u.y);
        acc.x += v0.x; acc.y += v0.y; acc.z += v1.x; acc.w += v1.y;
    }

    float4 b = ((const float4*)b1)[lane];
    float v[4];
    v[0] = fmaxf(fmaf(acc.x, dc, b.x), 0.f);
    v[1] = fmaxf(fmaf(acc.y, dc, b.y), 0.f);
    v[2] = fmaxf(fmaf(acc.z, dc, b.z), 0.f);
    v[3] = fmaxf(fmaf(acc.w, dc, b.w), 0.f);

    float p[16];
    #pragma unroll
    for (int j = 0; j < 16; j++) p[j] = 0.f;

    #pragma unroll
    for (int q = 0; q < 4; q++) {
        int k = lane * 4 + q;
        #pragma unroll
        for (int j4 = 0; j4 < 4; j4++) {
            float4 ww = ((const float4*)W2)[k * 4 + j4];
            p[j4 * 4 + 0] = fmaf(v[q], ww.x, p[j4 * 4 + 0]);
            p[j4 * 4 + 1] = fmaf(v[q], ww.y, p[j4 * 4 + 1]);
            p[j4 * 4 + 2] = fmaf(v[q], ww.z, p[j4 * 4 + 2]);
            p[j4 * 4 + 3] = fmaf(v[q], ww.w, p[j4 * 4 + 3]);
        }
    }

    #pragma unroll
    for (int off = 16; off >= 1; off >>= 1)
        #pragma unroll
        for (int j = 0; j < 16; j++)
            p[j] += __shfl_xor_sync(0xffffffffu, p[j], off);

    if (lane < 16) ((float*)g_h2)[row * F2 + lane] = p[lane] * dc;   // pre-scaled
}

// ---------------------------------------------------------------------------
// 6) fused layer-2: gather pre-scaled h2s + bias + log_softmax.
//    acc = dc * (h2s[row] + sum h2s[r]) + b2
// ---------------------------------------------------------------------------
__global__ __launch_bounds__(256) void k_layer2(const float* __restrict__ b2,
                                                float* __restrict__ out) {
    int row  = (blockIdx.x * 256 + threadIdx.x) >> 5;
    int lane = threadIdx.x & 31;
    if (row >= N_NODES) return;

    int j = lane & 15;
    float dc = g_dinv[row];

    const float* h2 = (const float*)g_h2;
    float acc = h2[row * F2 + j];                       // self term (h2s[row])

    int e0 = (row > 0) ? g_off[row - 1] : 0;
    int e1 = g_off[row];
    int r_nxt = (e0 < e1) ? g_src[e0] : 0;
    for (int e = e0; e < e1; e++) {
        int r = r_nxt;
        r_nxt = g_src[(e + 1 < e1) ? e + 1 : e];
        acc += h2[r * F2 + j];
    }
    acc = fmaf(acc, dc, b2[j]);

    float m = acc;
    #pragma unroll
    for (int off = 8; off >= 1; off >>= 1)
        m = fmaxf(m, __shfl_xor_sync(0xffffffffu, m, off));

    float s = __expf(acc - m);
    #pragma unroll
    for (int off = 8; off >= 1; off >>= 1)
        s += __shfl_xor_sync(0xffffffffu, s, off);

    if (lane < 16) out[row * F2 + lane] = (acc - m) - logf(s);
}

// ---------------------------------------------------------------------------
extern "C" void kernel_launch(void* const* d_in, const int* in_sizes, int n_in,
                              void* d_out, int out_size) {
    const float* x  = (const float*)d_in[0];
    const int*   ei = (const int*)d_in[1];     // int32 (JAX x64 disabled)
    const float* W1 = (const float*)d_in[2];
    const float* b1 = (const float*)d_in[3];
    const float* W2 = (const float*)d_in[4];
    const float* b2 = (const float*)d_in[5];
    float* out = (float*)d_out;

    (void)in_sizes; (void)n_in; (void)out_size;

    k_count <<<(N_EDGES / 4 + 255) / 256, 256>>>(ei);
    k_scan  <<<NB, TILE>>>();
    k_fill  <<<(N_EDGES / 4 + 255) / 256, 256>>>(ei);
    k_gemm1 <<<(N_NODES + 63) / 64, 128>>>(x, W1);
    k_layer1<<<(N_NODES * 32 + 255) / 256, 256>>>(b1, W2);
    k_layer2<<<(N_NODES * 32 + 255) / 256, 256>>>(b2, out);
}

// round 15
// speedup vs baseline: 1.1433x; 1.0318x over previous
#include <cuda_runtime.h>
#include <cuda_fp16.h>

#define N_NODES 50000
#define N_EDGES 800000
#define F1 128
#define F2 16

#define TILE 512
#define NB   ((N_NODES + TILE - 1) / TILE)   // 98

// Scratch (allocation-free contract: __device__ globals)
__device__ int       g_cnt [N_NODES];        // zero at load; self-re-zeroed
__device__ int       g_off [N_NODES + 1];    // exclusive offsets (NOT mutated)
__device__ long long g_state[NB];            // scan lookback
__device__ int4      g_pos4[N_EDGES / 4];    // per-edge slot within its dst node
__device__ int       g_src [N_EDGES];
__device__ float     g_dinv[N_NODES];
__device__ __align__(16) __half2 g_h1h[N_NODES * (F1 / 2)];  // h1 * dinv[row], fp16
__device__ float4    g_h2  [N_NODES * (F2 / 4)];             // h2 * dinv[row], fp32

// ---------------------------------------------------------------------------
// 1) in-degree counts; atomicAdd return value = this edge's slot in its node.
// ---------------------------------------------------------------------------
__global__ void k_count(const int* __restrict__ ei) {
    int e4 = blockIdx.x * blockDim.x + threadIdx.x;
    if (e4 < N_EDGES / 4) {
        int4 c = ((const int4*)(ei + N_EDGES))[e4];
        int4 p = make_int4(0, 0, 0, 0);
        if ((unsigned)c.x < N_NODES) p.x = atomicAdd(&g_cnt[c.x], 1);
        if ((unsigned)c.y < N_NODES) p.y = atomicAdd(&g_cnt[c.y], 1);
        if ((unsigned)c.z < N_NODES) p.z = atomicAdd(&g_cnt[c.z], 1);
        if ((unsigned)c.w < N_NODES) p.w = atomicAdd(&g_cnt[c.w], 1);
        g_pos4[e4] = p;
    }
}

// ---------------------------------------------------------------------------
// 2) single-kernel scan with decoupled lookback (98 blocks, all wave-1).
//    Fused: dinv = rsqrt(cnt+1); g_cnt self-zeroed (replay determinism).
//    Writes g_off[0..N] (exclusive prefix + grand total).
// ---------------------------------------------------------------------------
__global__ __launch_bounds__(TILE) void k_scan() {
    __shared__ int sh[TILE];
    __shared__ int s_ex;
    int t = threadIdx.x, bid = blockIdx.x;
    int i = bid * TILE + t;

    int c = (i < N_NODES) ? g_cnt[i] : 0;
    if (i < N_NODES) { g_dinv[i] = rsqrtf((float)(c + 1)); g_cnt[i] = 0; }

    sh[t] = c;
    __syncthreads();
    #pragma unroll
    for (int off = 1; off < TILE; off <<= 1) {
        int u = (t >= off) ? sh[t - off] : 0;
        __syncthreads();
        sh[t] += u;
        __syncthreads();
    }
    int total = sh[TILE - 1];

    if (t == 0) {
        long long st = (bid == 0)
            ? ((2LL << 32) | (unsigned)total)
            : ((1LL << 32) | (unsigned)total);
        atomicExch((unsigned long long*)&g_state[bid], (unsigned long long)st);
        if (bid == 0) s_ex = 0;
    }

    if (bid > 0 && t < 32) {
        int ex = 0, base = bid - 1;
        while (true) {
            int j = base - t;
            long long st;
            if (j >= 0) st = *(volatile long long*)&g_state[j];
            else        st = (2LL << 32);
            int flag = (int)(st >> 32);
            int val  = (int)(st & 0xffffffffLL);
            unsigned rdy = __ballot_sync(0xffffffffu, flag != 0);
            if (rdy != 0xffffffffu) continue;
            unsigned pref = __ballot_sync(0xffffffffu, flag == 2);
            int firstP = (pref == 0) ? 32 : (__ffs(pref) - 1);
            int contrib = (t <= firstP) ? val : 0;
            #pragma unroll
            for (int o = 16; o >= 1; o >>= 1)
                contrib += __shfl_xor_sync(0xffffffffu, contrib, o);
            ex += contrib;
            if (firstP < 32) break;
            base -= 32;
        }
        if (t == 0) {
            s_ex = ex;
            atomicExch((unsigned long long*)&g_state[bid],
                       (unsigned long long)((2LL << 32) | (unsigned)(ex + total)));
        }
    }
    __syncthreads();
    if (i < N_NODES) g_off[i] = s_ex + sh[t] - c;
    if (i == N_NODES - 1) g_off[N_NODES] = s_ex + sh[t];
}

// ---------------------------------------------------------------------------
// 3) fill source lists — NO atomics: slot = off[c] + pos[e].
//    Re-zero g_state for next replay.
// ---------------------------------------------------------------------------
__global__ void k_fill(const int* __restrict__ ei) {
    int t = blockIdx.x * blockDim.x + threadIdx.x;
    if (t < NB) g_state[t] = 0;
    if (t < N_EDGES / 4) {
        int4 r = ((const int4*)ei)[t];
        int4 c = ((const int4*)(ei + N_EDGES))[t];
        int4 p = g_pos4[t];
        if ((unsigned)r.x < N_NODES && (unsigned)c.x < N_NODES)
            g_src[g_off[c.x] + p.x] = r.x;
        if ((unsigned)r.y < N_NODES && (unsigned)c.y < N_NODES)
            g_src[g_off[c.y] + p.y] = r.y;
        if ((unsigned)r.z < N_NODES && (unsigned)c.z < N_NODES)
            g_src[g_off[c.z] + p.z] = r.z;
        if ((unsigned)r.w < N_NODES && (unsigned)c.w < N_NODES)
            g_src[g_off[c.w] + p.w] = r.w;
    }
}

// ---------------------------------------------------------------------------
// 4) h1s = (x @ W1) * dinv[row], fp16, via fp16 mma.sync m16n8k16.
//    64 rows / 128 threads per block. W packed as k-pairs {W[2k][n],W[2k+1][n]}
//    so each B fragment register is a single LDS.32. Pads chosen for zero
//    bank conflicts (xs stride 36: bank=4g+tig; ws stride 136: bank=8tig+g).
// ---------------------------------------------------------------------------
__global__ __launch_bounds__(128) void k_gemm1(const float* __restrict__ x,
                                               const float* __restrict__ W) {
    __shared__ __half2 xs[64 * 36];    // [row][kp]  kp = k/2 within chunk (0..31)
    __shared__ __half2 ws[32 * 136];   // [kp][n]    element = {W[2k][n], W[2k+1][n]}

    const int tid  = threadIdx.x;
    const int warp = tid >> 5;       // 0..3
    const int lane = tid & 31;
    const int g    = lane >> 2;      // 0..7
    const int tig  = lane & 3;       // 0..3
    const int row0 = blockIdx.x * 64;

    float c[16][4];
    #pragma unroll
    for (int nt = 0; nt < 16; nt++)
        #pragma unroll
        for (int q = 0; q < 4; q++) c[nt][q] = 0.f;

    const float4* x4 = (const float4*)x;
    const float4* W4 = (const float4*)W;

    for (int kc = 0; kc < 2; kc++) {             // K chunks of 64
        // stage x: 64 rows x 16 float4 (-> 32 half2 cols)
        #pragma unroll
        for (int it = 0; it < 8; it++) {
            int idx = it * 128 + tid;            // 0..1023
            int r   = idx >> 4;
            int c4  = idx & 15;
            float4 v = make_float4(0.f, 0.f, 0.f, 0.f);
            if (row0 + r < N_NODES)
                v = x4[(size_t)(row0 + r) * 32 + kc * 16 + c4];
            xs[r * 36 + c4 * 2 + 0] = __floats2half2_rn(v.x, v.y);
            xs[r * 36 + c4 * 2 + 1] = __floats2half2_rn(v.z, v.w);
        }
        // stage W: kp 0..31 (global k rows kc*64+2kp, +1), packed as k-pairs
        #pragma unroll
        for (int it = 0; it < 8; it++) {
            int idx = it * 128 + tid;            // 0..1023
            int kp  = idx >> 5;
            int n4  = idx & 31;
            int k0  = kc * 64 + kp * 2;
            float4 va = W4[(size_t)k0 * 32 + n4];
            float4 vb = W4[(size_t)(k0 + 1) * 32 + n4];
            __half2* d = &ws[kp * 136 + n4 * 4];
            d[0] = __floats2half2_rn(va.x, vb.x);
            d[1] = __floats2half2_rn(va.y, vb.y);
            d[2] = __floats2half2_rn(va.z, vb.z);
            d[3] = __floats2half2_rn(va.w, vb.w);
        }
        __syncthreads();

        #pragma unroll
        for (int ks = 0; ks < 4; ks++) {         // 4 x k16 per chunk
            int ar = (warp * 16 + g) * 36 + ks * 8 + tig;
            unsigned a0 = *(const unsigned*)&xs[ar];
            unsigned a1 = *(const unsigned*)&xs[ar + 8 * 36];
            unsigned a2 = *(const unsigned*)&xs[ar + 4];
            unsigned a3 = *(const unsigned*)&xs[ar + 8 * 36 + 4];

            int b0r = (ks * 8 + tig) * 136 + g;
            int b1r = (ks * 8 + tig + 4) * 136 + g;
            #pragma unroll
            for (int nt = 0; nt < 16; nt++) {
                unsigned b0 = *(const unsigned*)&ws[b0r + nt * 8];
                unsigned b1 = *(const unsigned*)&ws[b1r + nt * 8];
                asm("mma.sync.aligned.m16n8k16.row.col.f32.f16.f16.f32 "
                    "{%0,%1,%2,%3}, {%4,%5,%6,%7}, {%8,%9}, {%0,%1,%2,%3};"
                    : "+f"(c[nt][0]), "+f"(c[nt][1]), "+f"(c[nt][2]), "+f"(c[nt][3])
                    : "r"(a0), "r"(a1), "r"(a2), "r"(a3), "r"(b0), "r"(b1));
            }
        }
        __syncthreads();
    }

    // store fp16, pre-scaled by dinv[row]
    int ma = row0 + warp * 16 + g;
    int mb = ma + 8;
    float da = (ma < N_NODES) ? g_dinv[ma] : 0.f;
    float db = (mb < N_NODES) ? g_dinv[mb] : 0.f;
    #pragma unroll
    for (int nt = 0; nt < 16; nt++) {
        int c2 = nt * 4 + tig;                   // half2 column (of 64)
        if (ma < N_NODES)
            g_h1h[(size_t)ma * 64 + c2] = __floats2half2_rn(c[nt][0] * da, c[nt][1] * da);
        if (mb < N_NODES)
            g_h1h[(size_t)mb * 64 + c2] = __floats2half2_rn(c[nt][2] * db, c[nt][3] * db);
    }
}

// ---------------------------------------------------------------------------
// 5) fused layer-1: gather pre-scaled h1s + bias + ReLU + @W2.
// ---------------------------------------------------------------------------
__global__ __launch_bounds__(256) void k_layer1(const float* __restrict__ b1,
                                                const float* __restrict__ W2) {
    int row  = (blockIdx.x * 256 + threadIdx.x) >> 5;
    int lane = threadIdx.x & 31;
    if (row >= N_NODES) return;

    float dc = g_dinv[row];

    const uint2* h1v = (const uint2*)g_h1h;     // 4 halfs per element

    uint2  su = h1v[(size_t)row * 32 + lane];
    float2 s0 = __half22float2(*(__half2*)&su.x);
    float2 s1 = __half22float2(*(__half2*)&su.y);
    float4 acc = make_float4(s0.x, s0.y, s1.x, s1.y);   // self term

    int e0 = g_off[row];
    int e1 = g_off[row + 1];
    int r_nxt = (e0 < e1) ? g_src[e0] : 0;
    for (int e = e0; e < e1; e++) {
        int r = r_nxt;
        r_nxt = g_src[(e + 1 < e1) ? e + 1 : e];        // branchless prefetch
        uint2  u  = h1v[(size_t)r * 32 + lane];
        float2 v0 = __half22float2(*(__half2*)&u.x);
        float2 v1 = __half22float2(*(__half2*)&u.y);
        acc.x += v0.x; acc.y += v0.y; acc.z += v1.x; acc.w += v1.y;
    }

    float4 b = ((const float4*)b1)[lane];
    float v[4];
    v[0] = fmaxf(fmaf(acc.x, dc, b.x), 0.f);
    v[1] = fmaxf(fmaf(acc.y, dc, b.y), 0.f);
    v[2] = fmaxf(fmaf(acc.z, dc, b.z), 0.f);
    v[3] = fmaxf(fmaf(acc.w, dc, b.w), 0.f);

    float p[16];
    #pragma unroll
    for (int j = 0; j < 16; j++) p[j] = 0.f;

    #pragma unroll
    for (int q = 0; q < 4; q++) {
        int k = lane * 4 + q;
        #pragma unroll
        for (int j4 = 0; j4 < 4; j4++) {
            float4 ww = ((const float4*)W2)[k * 4 + j4];
            p[j4 * 4 + 0] = fmaf(v[q], ww.x, p[j4 * 4 + 0]);
            p[j4 * 4 + 1] = fmaf(v[q], ww.y, p[j4 * 4 + 1]);
            p[j4 * 4 + 2] = fmaf(v[q], ww.z, p[j4 * 4 + 2]);
            p[j4 * 4 + 3] = fmaf(v[q], ww.w, p[j4 * 4 + 3]);
        }
    }

    #pragma unroll
    for (int off = 16; off >= 1; off >>= 1)
        #pragma unroll
        for (int j = 0; j < 16; j++)
            p[j] += __shfl_xor_sync(0xffffffffu, p[j], off);

    if (lane < 16) ((float*)g_h2)[row * F2 + lane] = p[lane] * dc;   // pre-scaled
}

// ---------------------------------------------------------------------------
// 6) fused layer-2: gather pre-scaled h2s + bias + log_softmax.
// ---------------------------------------------------------------------------
__global__ __launch_bounds__(256) void k_layer2(const float* __restrict__ b2,
                                                float* __restrict__ out) {
    int row  = (blockIdx.x * 256 + threadIdx.x) >> 5;
    int lane = threadIdx.x & 31;
    if (row >= N_NODES) return;

    int j = lane & 15;
    float dc = g_dinv[row];

    const float* h2 = (const float*)g_h2;
    float acc = h2[row * F2 + j];                       // self term

    int e0 = g_off[row];
    int e1 = g_off[row + 1];
    int r_nxt = (e0 < e1) ? g_src[e0] : 0;
    for (int e = e0; e < e1; e++) {
        int r = r_nxt;
        r_nxt = g_src[(e + 1 < e1) ? e + 1 : e];
        acc += h2[r * F2 + j];
    }
    acc = fmaf(acc, dc, b2[j]);

    float m = acc;
    #pragma unroll
    for (int off = 8; off >= 1; off >>= 1)
        m = fmaxf(m, __shfl_xor_sync(0xffffffffu, m, off));

    float s = __expf(acc - m);
    #pragma unroll
    for (int off = 8; off >= 1; off >>= 1)
        s += __shfl_xor_sync(0xffffffffu, s, off);

    if (lane < 16) out[row * F2 + lane] = (acc - m) - logf(s);
}

// ---------------------------------------------------------------------------
extern "C" void kernel_launch(void* const* d_in, const int* in_sizes, int n_in,
                              void* d_out, int out_size) {
    const float* x  = (const float*)d_in[0];
    const int*   ei = (const int*)d_in[1];     // int32 (JAX x64 disabled)
    const float* W1 = (const float*)d_in[2];
    const float* b1 = (const float*)d_in[3];
    const float* W2 = (const float*)d_in[4];
    const float* b2 = (const float*)d_in[5];
    float* out = (float*)d_out;

    (void)in_sizes; (void)n_in; (void)out_size;

    k_count <<<(N_EDGES / 4 + 255) / 256, 256>>>(ei);
    k_scan  <<<NB, TILE>>>();
    k_fill  <<<(N_EDGES / 4 + 255) / 256, 256>>>(ei);
    k_gemm1 <<<(N_NODES + 63) / 64, 128>>>(x, W1);
    k_layer1<<<(N_NODES * 32 + 255) / 256, 256>>>(b1, W2);
    k_layer2<<<(N_NODES * 32 + 255) / 256, 256>>>(b2, out);
}

// round 16
// speedup vs baseline: 1.1437x; 1.0004x over previous
#include <cuda_runtime.h>
#include <cuda_fp16.h>

#define N_NODES 50000
#define N_EDGES 800000
#define F1 128
#define F2 16

#define TILE 512
#define NB   ((N_NODES + TILE - 1) / TILE)   // 98

// Scratch (allocation-free contract: __device__ globals)
__device__ int       g_cnt [N_NODES];        // zero at load; self-re-zeroed
__device__ int       g_off [N_NODES + 1];    // exclusive offsets (NOT mutated)
__device__ long long g_state[NB];            // scan lookback
__device__ int4      g_pos4[N_EDGES / 4];    // per-edge slot within its dst node
__device__ int       g_src [N_EDGES];
__device__ float     g_dinv[N_NODES];
__device__ __align__(16) __half2 g_h1h[N_NODES * (F1 / 2)];  // h1 * dinv[row], fp16
__device__ float4    g_h2  [N_NODES * (F2 / 4)];             // h2 * dinv[row], fp32

// ---------------------------------------------------------------------------
// 1) in-degree counts; atomicAdd return value = this edge's slot in its node.
// ---------------------------------------------------------------------------
__global__ void k_count(const int* __restrict__ ei) {
    int e4 = blockIdx.x * blockDim.x + threadIdx.x;
    if (e4 < N_EDGES / 4) {
        int4 c = ((const int4*)(ei + N_EDGES))[e4];
        int4 p = make_int4(0, 0, 0, 0);
        if ((unsigned)c.x < N_NODES) p.x = atomicAdd(&g_cnt[c.x], 1);
        if ((unsigned)c.y < N_NODES) p.y = atomicAdd(&g_cnt[c.y], 1);
        if ((unsigned)c.z < N_NODES) p.z = atomicAdd(&g_cnt[c.z], 1);
        if ((unsigned)c.w < N_NODES) p.w = atomicAdd(&g_cnt[c.w], 1);
        g_pos4[e4] = p;
    }
}

// ---------------------------------------------------------------------------
// 2) single-kernel scan with decoupled lookback (98 blocks, all wave-1).
//    Fused: dinv = rsqrt(cnt+1); g_cnt self-zeroed (replay determinism).
// ---------------------------------------------------------------------------
__global__ __launch_bounds__(TILE) void k_scan() {
    __shared__ int sh[TILE];
    __shared__ int s_ex;
    int t = threadIdx.x, bid = blockIdx.x;
    int i = bid * TILE + t;

    int c = (i < N_NODES) ? g_cnt[i] : 0;
    if (i < N_NODES) { g_dinv[i] = rsqrtf((float)(c + 1)); g_cnt[i] = 0; }

    sh[t] = c;
    __syncthreads();
    #pragma unroll
    for (int off = 1; off < TILE; off <<= 1) {
        int u = (t >= off) ? sh[t - off] : 0;
        __syncthreads();
        sh[t] += u;
        __syncthreads();
    }
    int total = sh[TILE - 1];

    if (t == 0) {
        long long st = (bid == 0)
            ? ((2LL << 32) | (unsigned)total)
            : ((1LL << 32) | (unsigned)total);
        atomicExch((unsigned long long*)&g_state[bid], (unsigned long long)st);
        if (bid == 0) s_ex = 0;
    }

    if (bid > 0 && t < 32) {
        int ex = 0, base = bid - 1;
        while (true) {
            int j = base - t;
            long long st;
            if (j >= 0) st = *(volatile long long*)&g_state[j];
            else        st = (2LL << 32);
            int flag = (int)(st >> 32);
            int val  = (int)(st & 0xffffffffLL);
            unsigned rdy = __ballot_sync(0xffffffffu, flag != 0);
            if (rdy != 0xffffffffu) continue;
            unsigned pref = __ballot_sync(0xffffffffu, flag == 2);
            int firstP = (pref == 0) ? 32 : (__ffs(pref) - 1);
            int contrib = (t <= firstP) ? val : 0;
            #pragma unroll
            for (int o = 16; o >= 1; o >>= 1)
                contrib += __shfl_xor_sync(0xffffffffu, contrib, o);
            ex += contrib;
            if (firstP < 32) break;
            base -= 32;
        }
        if (t == 0) {
            s_ex = ex;
            atomicExch((unsigned long long*)&g_state[bid],
                       (unsigned long long)((2LL << 32) | (unsigned)(ex + total)));
        }
    }
    __syncthreads();
    if (i < N_NODES) g_off[i] = s_ex + sh[t] - c;
    if (i == N_NODES - 1) g_off[N_NODES] = s_ex + sh[t];
}

// ---------------------------------------------------------------------------
// 3) fill source lists — NO atomics: slot = off[c] + pos[e].
// ---------------------------------------------------------------------------
__global__ void k_fill(const int* __restrict__ ei) {
    int t = blockIdx.x * blockDim.x + threadIdx.x;
    if (t < NB) g_state[t] = 0;
    if (t < N_EDGES / 4) {
        int4 r = ((const int4*)ei)[t];
        int4 c = ((const int4*)(ei + N_EDGES))[t];
        int4 p = g_pos4[t];
        if ((unsigned)r.x < N_NODES && (unsigned)c.x < N_NODES)
            g_src[g_off[c.x] + p.x] = r.x;
        if ((unsigned)r.y < N_NODES && (unsigned)c.y < N_NODES)
            g_src[g_off[c.y] + p.y] = r.y;
        if ((unsigned)r.z < N_NODES && (unsigned)c.z < N_NODES)
            g_src[g_off[c.z] + p.z] = r.z;
        if ((unsigned)r.w < N_NODES && (unsigned)c.w < N_NODES)
            g_src[g_off[c.w] + p.w] = r.w;
    }
}

// ---------------------------------------------------------------------------
// 4) h1s = (x @ W1) * dinv[row], fp16 mma m16n8k16.
//    256 threads / 8 warps per block, 64-row x 128-col tile, warps 4(M)x2(N):
//    each warp m16 x n64 -> 8 MMAs/k-step, 32 acc regs -> higher occupancy.
// ---------------------------------------------------------------------------
__global__ __launch_bounds__(256) void k_gemm1(const float* __restrict__ x,
                                               const float* __restrict__ W) {
    __shared__ __half2 xs[64 * 36];    // [row][kp]  kp = k/2 within chunk (0..31)
    __shared__ __half2 ws[32 * 136];   // [kp][n]    element = {W[2k][n], W[2k+1][n]}

    const int tid  = threadIdx.x;
    const int warp = tid >> 5;       // 0..7
    const int wm   = warp & 3;       // M tile 0..3
    const int wn   = warp >> 2;      // N half 0..1
    const int lane = tid & 31;
    const int g    = lane >> 2;      // 0..7
    const int tig  = lane & 3;       // 0..3
    const int row0 = blockIdx.x * 64;

    float c[8][4];
    #pragma unroll
    for (int nt = 0; nt < 8; nt++)
        #pragma unroll
        for (int q = 0; q < 4; q++) c[nt][q] = 0.f;

    const float4* x4 = (const float4*)x;
    const float4* W4 = (const float4*)W;

    for (int kc = 0; kc < 2; kc++) {             // K chunks of 64
        // stage x: 64 rows x 16 float4 (-> 32 half2 cols)
        #pragma unroll
        for (int it = 0; it < 4; it++) {
            int idx = it * 256 + tid;            // 0..1023
            int r   = idx >> 4;
            int c4  = idx & 15;
            float4 v = make_float4(0.f, 0.f, 0.f, 0.f);
            if (row0 + r < N_NODES)
                v = x4[(size_t)(row0 + r) * 32 + kc * 16 + c4];
            xs[r * 36 + c4 * 2 + 0] = __floats2half2_rn(v.x, v.y);
            xs[r * 36 + c4 * 2 + 1] = __floats2half2_rn(v.z, v.w);
        }
        // stage W: kp 0..31, packed as k-pairs {W[2k][n], W[2k+1][n]}
        #pragma unroll
        for (int it = 0; it < 4; it++) {
            int idx = it * 256 + tid;            // 0..1023
            int kp  = idx >> 5;
            int n4  = idx & 31;
            int k0  = kc * 64 + kp * 2;
            float4 va = W4[(size_t)k0 * 32 + n4];
            float4 vb = W4[(size_t)(k0 + 1) * 32 + n4];
            __half2* d = &ws[kp * 136 + n4 * 4];
            d[0] = __floats2half2_rn(va.x, vb.x);
            d[1] = __floats2half2_rn(va.y, vb.y);
            d[2] = __floats2half2_rn(va.z, vb.z);
            d[3] = __floats2half2_rn(va.w, vb.w);
        }
        __syncthreads();

        #pragma unroll
        for (int ks = 0; ks < 4; ks++) {         // 4 x k16 per chunk
            int ar = (wm * 16 + g) * 36 + ks * 8 + tig;
            unsigned a0 = *(const unsigned*)&xs[ar];
            unsigned a1 = *(const unsigned*)&xs[ar + 8 * 36];
            unsigned a2 = *(const unsigned*)&xs[ar + 4];
            unsigned a3 = *(const unsigned*)&xs[ar + 8 * 36 + 4];

            int b0r = (ks * 8 + tig) * 136 + wn * 64 + g;
            int b1r = (ks * 8 + tig + 4) * 136 + wn * 64 + g;
            #pragma unroll
            for (int nt = 0; nt < 8; nt++) {
                unsigned b0 = *(const unsigned*)&ws[b0r + nt * 8];
                unsigned b1 = *(const unsigned*)&ws[b1r + nt * 8];
                asm("mma.sync.aligned.m16n8k16.row.col.f32.f16.f16.f32 "
                    "{%0,%1,%2,%3}, {%4,%5,%6,%7}, {%8,%9}, {%0,%1,%2,%3};"
                    : "+f"(c[nt][0]), "+f"(c[nt][1]), "+f"(c[nt][2]), "+f"(c[nt][3])
                    : "r"(a0), "r"(a1), "r"(a2), "r"(a3), "r"(b0), "r"(b1));
            }
        }
        __syncthreads();
    }

    // store fp16, pre-scaled by dinv[row]
    int ma = row0 + wm * 16 + g;
    int mb = ma + 8;
    float da = (ma < N_NODES) ? g_dinv[ma] : 0.f;
    float db = (mb < N_NODES) ? g_dinv[mb] : 0.f;
    #pragma unroll
    for (int nt = 0; nt < 8; nt++) {
        int c2 = wn * 32 + nt * 4 + tig;         // half2 column (of 64)
        if (ma < N_NODES)
            g_h1h[(size_t)ma * 64 + c2] = __floats2half2_rn(c[nt][0] * da, c[nt][1] * da);
        if (mb < N_NODES)
            g_h1h[(size_t)mb * 64 + c2] = __floats2half2_rn(c[nt][2] * db, c[nt][3] * db);
    }
}

// ---------------------------------------------------------------------------
// 5) fused layer-1: gather pre-scaled h1s + bias + ReLU + @W2.
// ---------------------------------------------------------------------------
__global__ __launch_bounds__(256) void k_layer1(const float* __restrict__ b1,
                                                const float* __restrict__ W2) {
    int row  = (blockIdx.x * 256 + threadIdx.x) >> 5;
    int lane = threadIdx.x & 31;
    if (row >= N_NODES) return;

    float dc = g_dinv[row];

    const uint2* h1v = (const uint2*)g_h1h;     // 4 halfs per element

    uint2  su = h1v[(size_t)row * 32 + lane];
    float2 s0 = __half22float2(*(__half2*)&su.x);
    float2 s1 = __half22float2(*(__half2*)&su.y);
    float4 acc = make_float4(s0.x, s0.y, s1.x, s1.y);   // self term

    int e0 = g_off[row];
    int e1 = g_off[row + 1];
    int r_nxt = (e0 < e1) ? g_src[e0] : 0;
    for (int e = e0; e < e1; e++) {
        int r = r_nxt;
        r_nxt = g_src[(e + 1 < e1) ? e + 1 : e];        // branchless prefetch
        uint2  u  = h1v[(size_t)r * 32 + lane];
        float2 v0 = __half22float2(*(__half2*)&u.x);
        float2 v1 = __half22float2(*(__half2*)&u.y);
        acc.x += v0.x; acc.y += v0.y; acc.z += v1.x; acc.w += v1.y;
    }

    float4 b = ((const float4*)b1)[lane];
    float v[4];
    v[0] = fmaxf(fmaf(acc.x, dc, b.x), 0.f);
    v[1] = fmaxf(fmaf(acc.y, dc, b.y), 0.f);
    v[2] = fmaxf(fmaf(acc.z, dc, b.z), 0.f);
    v[3] = fmaxf(fmaf(acc.w, dc, b.w), 0.f);

    float p[16];
    #pragma unroll
    for (int j = 0; j < 16; j++) p[j] = 0.f;

    #pragma unroll
    for (int q = 0; q < 4; q++) {
        int k = lane * 4 + q;
        #pragma unroll
        for (int j4 = 0; j4 < 4; j4++) {
            float4 ww = ((const float4*)W2)[k * 4 + j4];
            p[j4 * 4 + 0] = fmaf(v[q], ww.x, p[j4 * 4 + 0]);
            p[j4 * 4 + 1] = fmaf(v[q], ww.y, p[j4 * 4 + 1]);
            p[j4 * 4 + 2] = fmaf(v[q], ww.z, p[j4 * 4 + 2]);
            p[j4 * 4 + 3] = fmaf(v[q], ww.w, p[j4 * 4 + 3]);
        }
    }

    #pragma unroll
    for (int off = 16; off >= 1; off >>= 1)
        #pragma unroll
        for (int j = 0; j < 16; j++)
            p[j] += __shfl_xor_sync(0xffffffffu, p[j], off);

    if (lane < 16) ((float*)g_h2)[row * F2 + lane] = p[lane] * dc;   // pre-scaled
}

// ---------------------------------------------------------------------------
// 6) fused layer-2: gather pre-scaled h2s + bias + log_softmax.
// ---------------------------------------------------------------------------
__global__ __launch_bounds__(256) void k_layer2(const float* __restrict__ b2,
                                                float* __restrict__ out) {
    int row  = (blockIdx.x * 256 + threadIdx.x) >> 5;
    int lane = threadIdx.x & 31;
    if (row >= N_NODES) return;

    int j = lane & 15;
    float dc = g_dinv[row];

    const float* h2 = (const float*)g_h2;
    float acc = h2[row * F2 + j];                       // self term

    int e0 = g_off[row];
    int e1 = g_off[row + 1];
    int r_nxt = (e0 < e1) ? g_src[e0] : 0;
    for (int e = e0; e < e1; e++) {
        int r = r_nxt;
        r_nxt = g_src[(e + 1 < e1) ? e + 1 : e];
        acc += h2[r * F2 + j];
    }
    acc = fmaf(acc, dc, b2[j]);

    float m = acc;
    #pragma unroll
    for (int off = 8; off >= 1; off >>= 1)
        m = fmaxf(m, __shfl_xor_sync(0xffffffffu, m, off));

    float s = __expf(acc - m);
    #pragma unroll
    for (int off = 8; off >= 1; off >>= 1)
        s += __shfl_xor_sync(0xffffffffu, s, off);

    if (lane < 16) out[row * F2 + lane] = (acc - m) - logf(s);
}

// ---------------------------------------------------------------------------
extern "C" void kernel_launch(void* const* d_in, const int* in_sizes, int n_in,
                              void* d_out, int out_size) {
    const float* x  = (const float*)d_in[0];
    const int*   ei = (const int*)d_in[1];     // int32 (JAX x64 disabled)
    const float* W1 = (const float*)d_in[2];
    const float* b1 = (const float*)d_in[3];
    const float* W2 = (const float*)d_in[4];
    const float* b2 = (const float*)d_in[5];
    float* out = (float*)d_out;

    (void)in_sizes; (void)n_in; (void)out_size;

    k_count <<<(N_EDGES / 4 + 255) / 256, 256>>>(ei);
    k_scan  <<<NB, TILE>>>();
    k_fill  <<<(N_EDGES / 4 + 255) / 256, 256>>>(ei);
    k_gemm1 <<<(N_NODES + 63) / 64, 256>>>(x, W1);
    k_layer1<<<(N_NODES * 32 + 255) / 256, 256>>>(b1, W2);
    k_layer2<<<(N_NODES * 32 + 255) / 256, 256>>>(b2, out);
}